// round 9
// baseline (speedup 1.0000x reference)
#include <cuda_runtime.h>
#include <cstdint>

#define A_DIM 512
#define T_DIM 128
#define I_DIM 768
#define H_DIM 256
#define S_TOTAL 65536            // T*A sequential steps per direction
#define GATE_COLS 2048           // 2 directions * 4H (permuted layout)
#define RING_CH 16               // xg ring: 16 chunks resident
#define RING_ROWS (RING_CH * 512)
#define RING_MASK (RING_ROWS - 1)

// ---------------- scratch (device globals: allocation-free, ~260 MB total) ----
__device__ float g_xg0[(size_t)RING_ROWS * GATE_COLS];  // 64 MB ring, layer0 gates
__device__ float g_xg1[(size_t)RING_ROWS * GATE_COLS];  // 64 MB ring, layer1 gates
__device__ float g_y [(size_t)S_TOTAL * 512];           // 128 MB, layer0 output
__device__ float g_z [512 * 512];                       // last-chunk layer1 output
__device__ int   g_prog_xg0[T_DIM];                     // ==64  when xg0 chunk ready
__device__ int   g_prog_y  [T_DIM];                     // ==128 when y chunk ready
__device__ int   g_prog_xg1[T_DIM];                     // ==64  when xg1 chunk ready
__device__ int   g_done0   [T_DIM];                     // ==16  when layer0 read chunk
__device__ int   g_done1   [T_DIM];                     // ==16  when layer1 read chunk

// ---------------- PTX helpers ----------------
static __device__ __forceinline__ uint32_t su32(const void* p) {
    uint32_t a;
    asm("{ .reg .u64 t; cvta.to.shared.u64 t, %1; cvt.u32.u64 %0, t; }" : "=r"(a) : "l"(p));
    return a;
}
static __device__ __forceinline__ uint32_t mapa_rank(uint32_t laddr, uint32_t rank) {
    uint32_t r;
    asm("mapa.shared::cluster.u32 %0, %1, %2;" : "=r"(r) : "r"(laddr), "r"(rank));
    return r;
}
static __device__ __forceinline__ void mbar_init(uint32_t bar, uint32_t cnt) {
    asm volatile("mbarrier.init.shared.b64 [%0], %1;" :: "r"(bar), "r"(cnt) : "memory");
}
// one arrival + add tx bytes to the CURRENT phase of a LOCAL barrier
static __device__ __forceinline__ void mbar_arm(uint32_t bar, uint32_t tx) {
    asm volatile("mbarrier.arrive.expect_tx.release.cluster.shared::cta.b64 _, [%0], %1;"
                 :: "r"(bar), "r"(tx) : "memory");
}
// single-hop: store 4 bytes into a peer CTA's SMEM AND complete 4 tx bytes on
// the mbarrier in that same peer CTA
static __device__ __forceinline__ void st_async32(uint32_t addr, float v, uint32_t mbar) {
    asm volatile("st.async.shared::cluster.mbarrier::complete_tx::bytes.b32 [%0], %1, [%2];"
                 :: "r"(addr), "r"(__float_as_uint(v)), "r"(mbar) : "memory");
}
static __device__ __forceinline__ void mbar_wait(uint32_t bar, uint32_t parity) {
    asm volatile(
        "{\n\t.reg .pred P;\n\t"
        "WL%=:\n\t"
        "mbarrier.try_wait.parity.acquire.cluster.shared::cta.b64 P, [%0], %1;\n\t"
        "@!P bra WL%=;\n\t}"
        :: "r"(bar), "r"(parity) : "memory");
}
#define CLUSTER_SYNC() do { \
    asm volatile("barrier.cluster.arrive.aligned;" ::: "memory"); \
    asm volatile("barrier.cluster.wait.aligned;"   ::: "memory"); \
} while (0)

static __device__ __forceinline__ int ld_acq(const int* p) {
    int v;
    asm volatile("ld.acquire.gpu.b32 %0, [%1];" : "=r"(v) : "l"(p) : "memory");
    return v;
}
static __device__ __forceinline__ void signal_rel(int* p) {
    __threadfence();
    atomicAdd(p, 1);
}
static __device__ __forceinline__ void wait_ge(const int* p, int target) {
    while (ld_acq(p) < target) __nanosleep(64);
}

static __device__ __forceinline__ unsigned long long pk2(float a, float b) {
    unsigned long long r;
    asm("mov.b64 %0, {%1, %2};" : "=l"(r) : "f"(a), "f"(b));
    return r;
}
static __device__ __forceinline__ void upk2(unsigned long long v, float& a, float& b) {
    asm("mov.b64 {%0, %1}, %2;" : "=f"(a), "=f"(b) : "l"(v));
}
static __device__ __forceinline__ void fma2(unsigned long long& d,
                                            unsigned long long a, unsigned long long b) {
    asm("fma.rn.f32x2 %0, %1, %2, %3;" : "=l"(d) : "l"(a), "l"(b), "l"(d));
}

static __device__ __forceinline__ float sigf(float x) {
    return __fdividef(1.f, 1.f + __expf(-x));
}
static __device__ __forceinline__ float tanhf_fast(float x) {
    return __fdividef(2.f, 1.f + __expf(-2.f * x)) - 1.f;
}

// xg column mapping (per direction block of 1024 cols):
//   cc = R*128 + w*16 + gate*4 + u  <->  whh row = gate*256 + R*32 + w*4 + u
static __device__ __forceinline__ int wrow_of(int cc) {
    return ((cc & 15) >> 2) * 256 + (cc >> 7) * 32 + (((cc >> 4) & 7) << 2) + (cc & 3);
}

// ---------------- init: zero progress counters (deterministic across replays) ----
__global__ void init_prog() {
    int i = threadIdx.x;
    if (i < T_DIM) {
        g_prog_xg0[i] = 0; g_prog_y[i] = 0; g_prog_xg1[i] = 0;
        g_done0[i] = 0;    g_done1[i] = 0;
    }
}

// ---------------- GEMM worker: chunk-ordered 128x128 tiles into a ring --------
static __device__ void gemm_worker(
    const float* __restrict__ Asrc, int xmode,
    const float* __restrict__ wF, const float* __restrict__ wB,
    const float* __restrict__ bF, const float* __restrict__ bB,
    int K, float* __restrict__ dst,
    const int* __restrict__ prog_dep, int dep_target,
    const int* __restrict__ free_dep,
    int* __restrict__ prog_out,
    int wid, int nworkers,
    float (*As)[128], float (*Bs)[128])
{
    const int tid = threadIdx.x;
    const int tx = tid & 15, ty = tid >> 4;
    const int lr = tid >> 1;
    const int lk = (tid & 1) * 4;

    for (int g = wid; g < 8192; g += nworkers) {
        const int tck = g >> 6, e = g & 63;
        const int rowB = ((tck << 2) + (e >> 4)) * 128;
        const int colB = (e & 15) * 128;

        if (tid == 0) {
            if (prog_dep) wait_ge(&prog_dep[tck], dep_target);
            if (tck >= RING_CH) wait_ge(&free_dep[tck - RING_CH], 16);
        }
        __syncthreads();

        const float* arow;
        {
            int r = rowB + lr;
            if (xmode) {  // x is [A, T, I]; step row s = t*512 + a -> x[a, t, :]
                int tt = r >> 9, aa = r & 511;
                arow = Asrc + (size_t)aa * (T_DIM * I_DIM) + (size_t)tt * I_DIM;
            } else {
                arow = Asrc + (size_t)r * 512;
            }
        }
        const float* brow;
        {
            int c = colB + lr;
            int d = c >> 10, cc = c & 1023;
            brow = (d ? wB : wF) + (size_t)wrow_of(cc) * K;
        }

        float acc[8][8];
        #pragma unroll
        for (int i = 0; i < 8; i++)
            #pragma unroll
            for (int j = 0; j < 8; j++) acc[i][j] = 0.f;

        for (int k0 = 0; k0 < K; k0 += 8) {
            __syncthreads();   // guards As/Bs reuse
            float4 av = *(const float4*)(arow + k0 + lk);
            float4 bv = *(const float4*)(brow + k0 + lk);
            As[lk + 0][lr] = av.x; As[lk + 1][lr] = av.y;
            As[lk + 2][lr] = av.z; As[lk + 3][lr] = av.w;
            Bs[lk + 0][lr] = bv.x; Bs[lk + 1][lr] = bv.y;
            Bs[lk + 2][lr] = bv.z; Bs[lk + 3][lr] = bv.w;
            __syncthreads();
            #pragma unroll
            for (int kk = 0; kk < 8; kk++) {
                float ar[8], br[8];
                #pragma unroll
                for (int i = 0; i < 8; i++) ar[i] = As[kk][ty * 8 + i];
                #pragma unroll
                for (int j = 0; j < 8; j++) br[j] = Bs[kk][tx * 8 + j];
                #pragma unroll
                for (int i = 0; i < 8; i++)
                    #pragma unroll
                    for (int j = 0; j < 8; j++) acc[i][j] = fmaf(ar[i], br[j], acc[i][j]);
            }
        }

        #pragma unroll
        for (int j = 0; j < 8; j++) {
            int c = colB + tx * 8 + j;
            int d = c >> 10, cc = c & 1023;
            float bb = __ldg((d ? bB : bF) + wrow_of(cc));
            #pragma unroll
            for (int i = 0; i < 8; i++) {
                int r = rowB + ty * 8 + i;
                dst[(size_t)(r & RING_MASK) * GATE_COLS + c] = acc[i][j] + bb;
            }
        }
        __syncthreads();   // all threads' global stores precede the release signal
        if (tid == 0) signal_rel(&prog_out[tck]);
    }
}

// ---------------- Recurrent runner (one CTA of an 8-CTA cluster) ----------------
// Single-hop handoff: bar[k] guards h slot k (count 8 = local warps' re-arms,
// tx 1024 B = 64 producer-warp st.async stores of 16 B each).
static __device__ void lstm_run(
    const float* __restrict__ whh, const float* __restrict__ xg,
    const int* __restrict__ prog_in, int* __restrict__ done_in,
    int* __restrict__ prog_out,
    int dir, int R, int lastOnly,
    float (*h_buf)[256], unsigned long long* mbars /*[2]*/)
{
    const int t     = threadIdx.x;
    const int w     = t >> 5;
    const int l     = t & 31;
    const int r     = l & 15;              // gate*4 + uidx
    const int khalf = l >> 4;
    const int gate  = r >> 2, uidx = r & 3;
    const int grow  = gate * 256 + R * 32 + w * 4 + uidx;   // row in whh [1024][256]
    const int dirMask = dir ? 511 : 0;                      // data row = s ^ dirMask

    // Whh slice -> registers, packed f32x2 (128 floats = 64 u64 per thread)
    unsigned long long wr_[64];
    {
        const float4* wp = (const float4*)(whh + (size_t)grow * 256 + khalf * 128);
        #pragma unroll
        for (int i = 0; i < 32; i++) {
            float4 v = wp[i];
            wr_[2 * i]     = pk2(v.x, v.y);
            wr_[2 * i + 1] = pk2(v.z, v.w);
        }
    }

    const uint32_t bar0 = su32(&mbars[0]);
    const uint32_t bar1 = su32(&mbars[1]);

    h_buf[0][t] = 0.f;                          // h0 = 0
    if (t == 0) { mbar_init(bar0, 8); mbar_init(bar1, 8); }
    __syncthreads();
    if (l == 0) { mbar_arm(bar0, 128); mbar_arm(bar1, 128); }  // arm phase 0 (8 warps)
    __syncthreads();
    CLUSTER_SYNC();                             // barriers armed before any remote store

    const uint32_t hb = su32(&h_buf[0][0]);
    uint32_t ph[8], pb0[8], pb1[8];
    #pragma unroll
    for (int j = 0; j < 8; j++) {
        ph[j]  = mapa_rank(hb, j);
        pb0[j] = mapa_rank(bar0, j);
        pb1[j] = mapa_rank(bar1, j);
    }

    // this lane's xg element: col = R*128 + w*16 + r (per direction block)
    const float* xgp = xg + (size_t)dir * 1024 + R * 128 + w * 16 + r;

    const int unit = R * 32 + w * 4 + l;        // valid for l < 4
    float c_reg = 0.f;
    float xc = 0.f, xn = 0.f;
    uint32_t p0 = 0, p1 = 0;                    // per-barrier wait parity

    for (int s = 0; s < S_TOTAL; s++) {
        if ((s & 511) == 0) {                   // chunk boundary
            int tck = s >> 9;
            if (t == 0) wait_ge(&prog_in[tck], 64);
            __syncthreads();                    // all warps past all chunk tck-1 reads
            if (t == 0 && tck > 0) signal_rel(&done_in[tck - 1]);
            xc = __ldg(xgp + (size_t)((s ^ dirMask) & RING_MASK) * GATE_COLS);
            xn = __ldg(xgp + (size_t)(((s + 1) ^ dirMask) & RING_MASK) * GATE_COLS);
        }
        float xf = 0.f;                         // speculative (discarded at boundary)
        if (s + 2 < S_TOTAL)
            xf = __ldg(xgp + (size_t)(((s + 2) ^ dirMask) & RING_MASK) * GATE_COLS);

        if (s > 0) {                            // wait for slot s&1 to be fully delivered
            if (s & 1) { mbar_wait(bar1, p1); p1 ^= 1; }
            else       { mbar_wait(bar0, p0); p0 ^= 1; }
        }

        // 128-MAC dot over this lane's k-half, dual accumulator chains
        const ulonglong2* hp = (const ulonglong2*)&h_buf[s & 1][khalf * 128];
        unsigned long long acc0 = 0ull, acc1 = 0ull;
        #pragma unroll
        for (int i = 0; i < 32; i++) {
            ulonglong2 hv = hp[i];
            fma2(acc0, wr_[2 * i],     hv.x);
            fma2(acc1, wr_[2 * i + 1], hv.y);
        }

        // re-arm bar[s&1] for its next phase; release orders the reads above,
        // so no peer store (guarded by this arm, causally after our broadcast
        // below) can overwrite slot s&1 before our reads are bound. s=0: init armed.
        if (s > 0 && l == 0) mbar_arm((s & 1) ? bar1 : bar0, 128);

        float a0, a1, a2, a3;
        upk2(acc0, a0, a1); upk2(acc1, a2, a3);
        float v = (a0 + a1) + (a2 + a3);
        v += __shfl_xor_sync(0xffffffffu, v, 16);       // combine k-halves
        float g = v + xc;
        xc = xn; xn = xf;

        // transpose gates to lanes 0..3 (lane u gets rows u, 4+u, 8+u, 12+u)
        int u = l & 3;
        float gi = __shfl_sync(0xffffffffu, g, u);
        float gf = __shfl_sync(0xffffffffu, g, 4 + u);
        float gg = __shfl_sync(0xffffffffu, g, 8 + u);
        float go = __shfl_sync(0xffffffffu, g, 12 + u);

        if (l < 4) {
            float fi = sigf(gi), ff = sigf(gf), fo = sigf(go), tg = tanhf_fast(gg);
            c_reg = ff * c_reg + fi * tg;
            float hn = fo * tanhf_fast(c_reg);

            int orow = s ^ dirMask;
            if (!lastOnly)
                g_y[(size_t)orow * 512 + dir * 256 + unit] = hn;
            else if (orow >= S_TOTAL - 512)
                g_z[(orow - (S_TOTAL - 512)) * 512 + dir * 256 + unit] = hn;

            // single-hop broadcast: data + tx-completion to all 8 peers' bar[(s+1)&1]
            uint32_t off = (uint32_t)((((s + 1) & 1) * 256 + unit) * 4);
            if ((s + 1) & 1) {
                #pragma unroll
                for (int j = 0; j < 8; j++) st_async32(ph[j] + off, hn, pb1[j]);
            } else {
                #pragma unroll
                for (int j = 0; j < 8; j++) st_async32(ph[j] + off, hn, pb0[j]);
            }
        }
        __syncwarp();                           // lanes 0-3 g_y stores precede signal
        if (prog_out && (s & 511) == 511 && l == 0)
            signal_rel(&prog_out[s >> 9]);      // this warp's y-chunk writes done
    }
    CLUSTER_SYNC();  // no CTA exits while peers may still write its SMEM
}

// ---------------- Persistent mega-kernel: layer0 || gemm0 || gemm1 || layer1 ----
__global__ void __launch_bounds__(256, 1) __cluster_dims__(8, 1, 1)
mega(const float* __restrict__ x,
     const float* __restrict__ wih0f, const float* __restrict__ wih0b,
     const float* __restrict__ b0f,   const float* __restrict__ b0b,
     const float* __restrict__ whh0f, const float* __restrict__ whh0b,
     const float* __restrict__ wih1f, const float* __restrict__ wih1b,
     const float* __restrict__ b1f,   const float* __restrict__ b1b,
     const float* __restrict__ whh1f, const float* __restrict__ whh1b)
{
    __shared__ float As[8][128];
    __shared__ float Bs[8][128];
    __shared__ __align__(16) float h_buf[2][256];
    __shared__ __align__(8) unsigned long long mbars[2];

    const int cta = blockIdx.x;
    if (cta < 16) {                       // layer0 recurrence (clusters 0,1)
        int dir = cta >> 3, R = cta & 7;
        lstm_run(dir ? whh0b : whh0f, g_xg0, g_prog_xg0, g_done0, g_prog_y,
                 dir, R, 0, h_buf, mbars);
    } else if (cta < 32) {                // layer1 recurrence (clusters 2,3)
        int c = cta - 16;
        int dir = c >> 3, R = c & 7;
        lstm_run(dir ? whh1b : whh1f, g_xg1, g_prog_xg1, g_done1, nullptr,
                 dir, R, 1, h_buf, mbars);
    } else if (cta < 64) {                // 32 workers: xg0 = x @ Wih0^T + b0
        gemm_worker(x, 1, wih0f, wih0b, b0f, b0b, I_DIM, g_xg0,
                    nullptr, 0, g_done0, g_prog_xg0, cta - 32, 32, As, Bs);
    } else {                              // 32 workers: xg1 = y @ Wih1^T + b1
        gemm_worker(g_y, 0, wih1f, wih1b, b1f, b1b, 512, g_xg1,
                    g_prog_y, 128, g_done1, g_prog_xg1, cta - 64, 32, As, Bs);
    }
}

// ---------------- Head: z[512,512] @ w1.T + b1 -> @ w2.T + b2 -> softmax(13) ----
__global__ void __launch_bounds__(128)
head_kernel(const float* __restrict__ w1, const float* __restrict__ b1,
            const float* __restrict__ w2, const float* __restrict__ b2,
            float* __restrict__ out)
{
    __shared__ float zr[512];
    __shared__ float hd[128];
    __shared__ float lg[16];
    const int a = blockIdx.x, t = threadIdx.x;

    for (int i = t; i < 512; i += 128) zr[i] = g_z[a * 512 + i];
    __syncthreads();

    float acc = __ldg(b1 + t);
    const float* wr = w1 + (size_t)t * 512;
    #pragma unroll 8
    for (int k = 0; k < 512; k++) acc = fmaf(__ldg(wr + k), zr[k], acc);
    hd[t] = acc;
    __syncthreads();

    if (t < 13) {
        float lgt = __ldg(b2 + t);
        const float* w2r = w2 + t * 128;
        #pragma unroll 8
        for (int k = 0; k < 128; k++) lgt = fmaf(__ldg(w2r + k), hd[k], lgt);
        lg[t] = lgt;
    }
    __syncthreads();
    if (t < 13) {
        float m = -1e30f;
        for (int j = 0; j < 13; j++) m = fmaxf(m, lg[j]);
        float ssum = 0.f;
        for (int j = 0; j < 13; j++) ssum += expf(lg[j] - m);
        out[a * 13 + t] = expf(lg[t] - m) / ssum;
    }
}

// ---------------- launch ----------------
extern "C" void kernel_launch(void* const* d_in, const int* in_sizes, int n_in,
                              void* d_out, int out_size)
{
    const float* x     = (const float*)d_in[0];
    const float* wih0f = (const float*)d_in[1];
    const float* whh0f = (const float*)d_in[2];
    const float* b0f   = (const float*)d_in[3];
    const float* wih0b = (const float*)d_in[4];
    const float* whh0b = (const float*)d_in[5];
    const float* b0b   = (const float*)d_in[6];
    const float* wih1f = (const float*)d_in[7];
    const float* whh1f = (const float*)d_in[8];
    const float* b1f   = (const float*)d_in[9];
    const float* wih1b = (const float*)d_in[10];
    const float* whh1b = (const float*)d_in[11];
    const float* b1b   = (const float*)d_in[12];
    const float* w1    = (const float*)d_in[13];
    const float* bias1 = (const float*)d_in[14];
    const float* w2    = (const float*)d_in[15];
    const float* bias2 = (const float*)d_in[16];
    float* out = (float*)d_out;

    init_prog<<<1, 128>>>();
    mega<<<96, 256>>>(x, wih0f, wih0b, b0f, b0b, whh0f, whh0b,
                      wih1f, wih1b, b1f, b1b, whh1f, whh1b);
    head_kernel<<<512, 128>>>(w1, bias1, w2, bias2, out);
}

// round 10
// speedup vs baseline: 1.0109x; 1.0109x over previous
#include <cuda_runtime.h>
#include <cstdint>

#define A_DIM 512
#define T_DIM 128
#define I_DIM 768
#define H_DIM 256
#define S_TOTAL 65536            // T*A sequential steps per direction
#define GATE_COLS 2048           // 2 directions * 4H (permuted layout)
#define RING_CH 16               // xg ring: 16 chunks resident
#define RING_ROWS (RING_CH * 512)
#define RING_MASK (RING_ROWS - 1)

// ---------------- scratch (device globals: allocation-free, ~260 MB total) ----
__device__ float g_xg0[(size_t)RING_ROWS * GATE_COLS];  // 64 MB ring, layer0 gates
__device__ float g_xg1[(size_t)RING_ROWS * GATE_COLS];  // 64 MB ring, layer1 gates
__device__ float g_y [(size_t)S_TOTAL * 512];           // 128 MB, layer0 output
__device__ float g_z [512 * 512];                       // last-chunk layer1 output
__device__ int   g_prog_xg0[T_DIM];                     // ==64  when xg0 chunk ready
__device__ int   g_prog_y  [T_DIM];                     // ==128 when y chunk ready
__device__ int   g_prog_xg1[T_DIM];                     // ==64  when xg1 chunk ready
__device__ int   g_done0   [T_DIM];                     // ==16  when layer0 read chunk
__device__ int   g_done1   [T_DIM];                     // ==16  when layer1 read chunk

// ---------------- PTX helpers ----------------
static __device__ __forceinline__ uint32_t su32(const void* p) {
    uint32_t a;
    asm("{ .reg .u64 t; cvta.to.shared.u64 t, %1; cvt.u32.u64 %0, t; }" : "=r"(a) : "l"(p));
    return a;
}
static __device__ __forceinline__ uint32_t mapa_rank(uint32_t laddr, uint32_t rank) {
    uint32_t r;
    asm("mapa.shared::cluster.u32 %0, %1, %2;" : "=r"(r) : "r"(laddr), "r"(rank));
    return r;
}
static __device__ __forceinline__ void st_cl_v4(uint32_t addr, float4 v) {
    asm volatile("st.shared::cluster.v4.f32 [%0], {%1, %2, %3, %4};"
                 :: "r"(addr), "f"(v.x), "f"(v.y), "f"(v.z), "f"(v.w) : "memory");
}
static __device__ __forceinline__ void mbar_init(uint32_t bar, uint32_t cnt) {
    asm volatile("mbarrier.init.shared.b64 [%0], %1;" :: "r"(bar), "r"(cnt) : "memory");
}
static __device__ __forceinline__ void arrive_rel(uint32_t remote_bar) {
    asm volatile("mbarrier.arrive.release.cluster.shared::cluster.b64 _, [%0];"
                 :: "r"(remote_bar) : "memory");
}
static __device__ __forceinline__ void mbar_wait(uint32_t bar, uint32_t parity) {
    asm volatile(
        "{\n\t.reg .pred P;\n\t"
        "WL%=:\n\t"
        "mbarrier.try_wait.parity.acquire.cluster.shared::cta.b64 P, [%0], %1;\n\t"
        "@!P bra WL%=;\n\t}"
        :: "r"(bar), "r"(parity) : "memory");
}
#define CLUSTER_SYNC() do { \
    asm volatile("barrier.cluster.arrive.aligned;" ::: "memory"); \
    asm volatile("barrier.cluster.wait.aligned;"   ::: "memory"); \
} while (0)

static __device__ __forceinline__ int ld_acq(const int* p) {
    int v;
    asm volatile("ld.acquire.gpu.b32 %0, [%1];" : "=r"(v) : "l"(p) : "memory");
    return v;
}
static __device__ __forceinline__ void signal_rel(int* p) {
    __threadfence();
    atomicAdd(p, 1);
}
static __device__ __forceinline__ void wait_ge(const int* p, int target) {
    while (ld_acq(p) < target) __nanosleep(64);
}

static __device__ __forceinline__ unsigned long long pk2(float a, float b) {
    unsigned long long r;
    asm("mov.b64 %0, {%1, %2};" : "=l"(r) : "f"(a), "f"(b));
    return r;
}
static __device__ __forceinline__ void upk2(unsigned long long v, float& a, float& b) {
    asm("mov.b64 {%0, %1}, %2;" : "=f"(a), "=f"(b) : "l"(v));
}
static __device__ __forceinline__ void fma2(unsigned long long& d,
                                            unsigned long long a, unsigned long long b) {
    asm("fma.rn.f32x2 %0, %1, %2, %3;" : "=l"(d) : "l"(a), "l"(b), "l"(d));
}

static __device__ __forceinline__ float sigf(float x) {
    return __fdividef(1.f, 1.f + __expf(-x));
}
static __device__ __forceinline__ float tanhf_fast(float x) {
    return __fdividef(2.f, 1.f + __expf(-2.f * x)) - 1.f;
}

// xg column mapping (per direction block of 1024 cols):
//   cc = R*128 + w*16 + gate*4 + u  <->  whh row = gate*256 + R*32 + w*4 + u
static __device__ __forceinline__ int wrow_of(int cc) {
    return ((cc & 15) >> 2) * 256 + (cc >> 7) * 32 + (((cc >> 4) & 7) << 2) + (cc & 3);
}

// ---------------- init: zero progress counters (deterministic across replays) ----
__global__ void init_prog() {
    int i = threadIdx.x;
    if (i < T_DIM) {
        g_prog_xg0[i] = 0; g_prog_y[i] = 0; g_prog_xg1[i] = 0;
        g_done0[i] = 0;    g_done1[i] = 0;
    }
}

// ---------------- GEMM worker: chunk-ordered 128x128 tiles into a ring --------
static __device__ void gemm_worker(
    const float* __restrict__ Asrc, int xmode,
    const float* __restrict__ wF, const float* __restrict__ wB,
    const float* __restrict__ bF, const float* __restrict__ bB,
    int K, float* __restrict__ dst,
    const int* __restrict__ prog_dep, int dep_target,
    const int* __restrict__ free_dep,
    int* __restrict__ prog_out,
    int wid, int nworkers,
    float (*As)[128], float (*Bs)[128])
{
    const int tid = threadIdx.x;
    const int tx = tid & 15, ty = tid >> 4;
    const int lr = tid >> 1;
    const int lk = (tid & 1) * 4;

    for (int g = wid; g < 8192; g += nworkers) {
        const int tck = g >> 6, e = g & 63;
        const int rowB = ((tck << 2) + (e >> 4)) * 128;
        const int colB = (e & 15) * 128;

        if (tid == 0) {
            if (prog_dep) wait_ge(&prog_dep[tck], dep_target);
            if (tck >= RING_CH) wait_ge(&free_dep[tck - RING_CH], 16);
        }
        __syncthreads();

        const float* arow;
        {
            int r = rowB + lr;
            if (xmode) {  // x is [A, T, I]; step row s = t*512 + a -> x[a, t, :]
                int tt = r >> 9, aa = r & 511;
                arow = Asrc + (size_t)aa * (T_DIM * I_DIM) + (size_t)tt * I_DIM;
            } else {
                arow = Asrc + (size_t)r * 512;
            }
        }
        const float* brow;
        {
            int c = colB + lr;
            int d = c >> 10, cc = c & 1023;
            brow = (d ? wB : wF) + (size_t)wrow_of(cc) * K;
        }

        float acc[8][8];
        #pragma unroll
        for (int i = 0; i < 8; i++)
            #pragma unroll
            for (int j = 0; j < 8; j++) acc[i][j] = 0.f;

        for (int k0 = 0; k0 < K; k0 += 8) {
            __syncthreads();   // guards As/Bs reuse
            float4 av = *(const float4*)(arow + k0 + lk);
            float4 bv = *(const float4*)(brow + k0 + lk);
            As[lk + 0][lr] = av.x; As[lk + 1][lr] = av.y;
            As[lk + 2][lr] = av.z; As[lk + 3][lr] = av.w;
            Bs[lk + 0][lr] = bv.x; Bs[lk + 1][lr] = bv.y;
            Bs[lk + 2][lr] = bv.z; Bs[lk + 3][lr] = bv.w;
            __syncthreads();
            #pragma unroll
            for (int kk = 0; kk < 8; kk++) {
                float ar[8], br[8];
                #pragma unroll
                for (int i = 0; i < 8; i++) ar[i] = As[kk][ty * 8 + i];
                #pragma unroll
                for (int j = 0; j < 8; j++) br[j] = Bs[kk][tx * 8 + j];
                #pragma unroll
                for (int i = 0; i < 8; i++)
                    #pragma unroll
                    for (int j = 0; j < 8; j++) acc[i][j] = fmaf(ar[i], br[j], acc[i][j]);
            }
        }

        #pragma unroll
        for (int j = 0; j < 8; j++) {
            int c = colB + tx * 8 + j;
            int d = c >> 10, cc = c & 1023;
            float bb = __ldg((d ? bB : bF) + wrow_of(cc));
            #pragma unroll
            for (int i = 0; i < 8; i++) {
                int r = rowB + ty * 8 + i;
                dst[(size_t)(r & RING_MASK) * GATE_COLS + c] = acc[i][j] + bb;
            }
        }
        __syncthreads();   // all threads' global stores precede the release signal
        if (tid == 0) signal_rel(&prog_out[tck]);
    }
}

// ---------------- Recurrent runner (one CTA of an 8-CTA cluster) ----------------
// Staged warp-per-peer broadcast: all warps stage their hn locally; after one
// __syncthreads, warp w ships the CTA's full 32-unit slice (128 B, one v4
// warp-instr) to peer w and release-arrives at peer w's barrier (count 8).
static __device__ void lstm_run(
    const float* __restrict__ whh, const float* __restrict__ xg,
    const int* __restrict__ prog_in, int* __restrict__ done_in,
    int* __restrict__ prog_out,
    int dir, int R, int lastOnly,
    float (*h_buf)[256], float (*stage)[32], unsigned long long* mbarp)
{
    const int t     = threadIdx.x;
    const int w     = t >> 5;
    const int l     = t & 31;
    const int r     = l & 15;              // gate*4 + uidx
    const int khalf = l >> 4;
    const int gate  = r >> 2, uidx = r & 3;
    const int grow  = gate * 256 + R * 32 + w * 4 + uidx;   // row in whh [1024][256]
    const int dirMask = dir ? 511 : 0;                      // data row = s ^ dirMask

    // Whh slice -> registers, packed f32x2 (128 floats = 64 u64 per thread)
    unsigned long long wr_[64];
    {
        const float4* wp = (const float4*)(whh + (size_t)grow * 256 + khalf * 128);
        #pragma unroll
        for (int i = 0; i < 32; i++) {
            float4 v = wp[i];
            wr_[2 * i]     = pk2(v.x, v.y);
            wr_[2 * i + 1] = pk2(v.z, v.w);
        }
    }

    h_buf[0][t] = 0.f;                          // h0 = 0
    if (t == 0) mbar_init(su32(mbarp), 8);      // 8 arrives/step: warp w of each CTA
    __syncthreads();
    CLUSTER_SYNC();                             // barriers visible cluster-wide

    const uint32_t hb  = su32(&h_buf[0][0]);
    const uint32_t bar = su32(mbarp);
    uint32_t ph[8], pb[8];
    #pragma unroll
    for (int j = 0; j < 8; j++) { ph[j] = mapa_rank(hb, j); pb[j] = mapa_rank(bar, j); }

    // this lane's xg element: col = R*128 + w*16 + r (per direction block)
    const float* xgp = xg + (size_t)dir * 1024 + R * 128 + w * 16 + r;

    const int unit = R * 32 + w * 4 + l;        // valid for l < 4
    float c_reg = 0.f;
    float xc = 0.f, xn = 0.f;

    for (int s = 0; s < S_TOTAL; s++) {
        if ((s & 511) == 0) {                   // chunk boundary
            int tck = s >> 9;
            if (t == 0) wait_ge(&prog_in[tck], 64);
            __syncthreads();                    // all warps past all chunk tck-1 reads
            if (t == 0 && tck > 0) signal_rel(&done_in[tck - 1]);
            xc = __ldg(xgp + (size_t)((s ^ dirMask) & RING_MASK) * GATE_COLS);
            xn = __ldg(xgp + (size_t)(((s + 1) ^ dirMask) & RING_MASK) * GATE_COLS);
        }
        float xf = 0.f;                         // speculative (discarded at boundary)
        if (s + 2 < S_TOTAL)
            xf = __ldg(xgp + (size_t)(((s + 2) ^ dirMask) & RING_MASK) * GATE_COLS);

        if (s > 0) mbar_wait(bar, (uint32_t)((s - 1) & 1));

        // 128-MAC dot over this lane's k-half, dual accumulator chains
        const ulonglong2* hp = (const ulonglong2*)&h_buf[s & 1][khalf * 128];
        unsigned long long acc0 = 0ull, acc1 = 0ull;
        #pragma unroll
        for (int i = 0; i < 32; i++) {
            ulonglong2 hv = hp[i];
            fma2(acc0, wr_[2 * i],     hv.x);
            fma2(acc1, wr_[2 * i + 1], hv.y);
        }
        float a0, a1, a2, a3;
        upk2(acc0, a0, a1); upk2(acc1, a2, a3);
        float v = (a0 + a1) + (a2 + a3);
        v += __shfl_xor_sync(0xffffffffu, v, 16);       // combine k-halves
        float g = v + xc;
        xc = xn; xn = xf;

        // transpose gates to lanes 0..3 (lane u gets rows u, 4+u, 8+u, 12+u)
        int u = l & 3;
        float gi = __shfl_sync(0xffffffffu, g, u);
        float gf = __shfl_sync(0xffffffffu, g, 4 + u);
        float gg = __shfl_sync(0xffffffffu, g, 8 + u);
        float go = __shfl_sync(0xffffffffu, g, 12 + u);

        const int sb = s & 1;                   // stage buffer parity
        if (l < 4) {
            float fi = sigf(gi), ff = sigf(gf), fo = sigf(go), tg = tanhf_fast(gg);
            c_reg = ff * c_reg + fi * tg;
            float hn = fo * tanhf_fast(c_reg);

            int orow = s ^ dirMask;
            if (!lastOnly)
                g_y[(size_t)orow * 512 + dir * 256 + unit] = hn;
            else if (orow >= S_TOTAL - 512)
                g_z[(orow - (S_TOTAL - 512)) * 512 + dir * 256 + unit] = hn;

            stage[sb][w * 4 + l] = hn;          // local staging (4 B STS)
        }
        __syncthreads();                        // all stage writes visible CTA-wide
        // warp w ships the CTA's full 32-unit slice to peer w (one 128 B message)
        if (l < 8) {
            float4 hv4 = ((const float4*)&stage[sb][0])[l];
            uint32_t dst = ph[w]
                         + (uint32_t)((((s + 1) & 1) * 256 + R * 32) * 4)
                         + (uint32_t)(l * 16);
            st_cl_v4(dst, hv4);
        }
        __syncwarp();                           // warp's stores precede its arrive
        if (prog_out && (s & 511) == 511 && l == 0)
            signal_rel(&prog_out[s >> 9]);      // this warp's y-chunk writes done
        if (l == 0) arrive_rel(pb[w]);          // warp w vouches for slice at peer w
    }
    CLUSTER_SYNC();  // no CTA exits while peers may still write its SMEM
}

// ---------------- Persistent mega-kernel: layer0 || gemm0 || gemm1 || layer1 ----
__global__ void __launch_bounds__(256, 1) __cluster_dims__(8, 1, 1)
mega(const float* __restrict__ x,
     const float* __restrict__ wih0f, const float* __restrict__ wih0b,
     const float* __restrict__ b0f,   const float* __restrict__ b0b,
     const float* __restrict__ whh0f, const float* __restrict__ whh0b,
     const float* __restrict__ wih1f, const float* __restrict__ wih1b,
     const float* __restrict__ b1f,   const float* __restrict__ b1b,
     const float* __restrict__ whh1f, const float* __restrict__ whh1b)
{
    __shared__ float As[8][128];
    __shared__ float Bs[8][128];
    __shared__ __align__(16) float h_buf[2][256];
    __shared__ __align__(16) float stage[2][32];
    __shared__ __align__(8) unsigned long long mbar;

    const int cta = blockIdx.x;
    if (cta < 16) {                       // layer0 recurrence (clusters 0,1)
        int dir = cta >> 3, R = cta & 7;
        lstm_run(dir ? whh0b : whh0f, g_xg0, g_prog_xg0, g_done0, g_prog_y,
                 dir, R, 0, h_buf, stage, &mbar);
    } else if (cta < 32) {                // layer1 recurrence (clusters 2,3)
        int c = cta - 16;
        int dir = c >> 3, R = c & 7;
        lstm_run(dir ? whh1b : whh1f, g_xg1, g_prog_xg1, g_done1, nullptr,
                 dir, R, 1, h_buf, stage, &mbar);
    } else if (cta < 64) {                // 32 workers: xg0 = x @ Wih0^T + b0
        gemm_worker(x, 1, wih0f, wih0b, b0f, b0b, I_DIM, g_xg0,
                    nullptr, 0, g_done0, g_prog_xg0, cta - 32, 32, As, Bs);
    } else {                              // 32 workers: xg1 = y @ Wih1^T + b1
        gemm_worker(g_y, 0, wih1f, wih1b, b1f, b1b, 512, g_xg1,
                    g_prog_y, 128, g_done1, g_prog_xg1, cta - 64, 32, As, Bs);
    }
}

// ---------------- Head: z[512,512] @ w1.T + b1 -> @ w2.T + b2 -> softmax(13) ----
__global__ void __launch_bounds__(128)
head_kernel(const float* __restrict__ w1, const float* __restrict__ b1,
            const float* __restrict__ w2, const float* __restrict__ b2,
            float* __restrict__ out)
{
    __shared__ float zr[512];
    __shared__ float hd[128];
    __shared__ float lg[16];
    const int a = blockIdx.x, t = threadIdx.x;

    for (int i = t; i < 512; i += 128) zr[i] = g_z[a * 512 + i];
    __syncthreads();

    float acc = __ldg(b1 + t);
    const float* wr = w1 + (size_t)t * 512;
    #pragma unroll 8
    for (int k = 0; k < 512; k++) acc = fmaf(__ldg(wr + k), zr[k], acc);
    hd[t] = acc;
    __syncthreads();

    if (t < 13) {
        float lgt = __ldg(b2 + t);
        const float* w2r = w2 + t * 128;
        #pragma unroll 8
        for (int k = 0; k < 128; k++) lgt = fmaf(__ldg(w2r + k), hd[k], lgt);
        lg[t] = lgt;
    }
    __syncthreads();
    if (t < 13) {
        float m = -1e30f;
        for (int j = 0; j < 13; j++) m = fmaxf(m, lg[j]);
        float ssum = 0.f;
        for (int j = 0; j < 13; j++) ssum += expf(lg[j] - m);
        out[a * 13 + t] = expf(lg[t] - m) / ssum;
    }
}

// ---------------- launch ----------------
extern "C" void kernel_launch(void* const* d_in, const int* in_sizes, int n_in,
                              void* d_out, int out_size)
{
    const float* x     = (const float*)d_in[0];
    const float* wih0f = (const float*)d_in[1];
    const float* whh0f = (const float*)d_in[2];
    const float* b0f   = (const float*)d_in[3];
    const float* wih0b = (const float*)d_in[4];
    const float* whh0b = (const float*)d_in[5];
    const float* b0b   = (const float*)d_in[6];
    const float* wih1f = (const float*)d_in[7];
    const float* whh1f = (const float*)d_in[8];
    const float* b1f   = (const float*)d_in[9];
    const float* wih1b = (const float*)d_in[10];
    const float* whh1b = (const float*)d_in[11];
    const float* b1b   = (const float*)d_in[12];
    const float* w1    = (const float*)d_in[13];
    const float* bias1 = (const float*)d_in[14];
    const float* w2    = (const float*)d_in[15];
    const float* bias2 = (const float*)d_in[16];
    float* out = (float*)d_out;

    init_prog<<<1, 128>>>();
    mega<<<96, 256>>>(x, wih0f, wih0b, b0f, b0b, whh0f, whh0b,
                      wih1f, wih1b, b1f, b1b, whh1f, whh1b);
    head_kernel<<<512, 128>>>(w1, bias1, w2, bias2, out);
}

// round 11
// speedup vs baseline: 1.1013x; 1.0895x over previous
#include <cuda_runtime.h>
#include <cstdint>

#define A_DIM 512
#define T_DIM 128
#define I_DIM 768
#define H_DIM 256
#define S_TOTAL 65536            // T*A sequential steps per direction
#define GATE_COLS 2048           // 2 directions * 4H (permuted layout)
#define RING_CH 16               // xg ring: 16 chunks resident
#define RING_ROWS (RING_CH * 512)
#define RING_MASK (RING_ROWS - 1)

// ---------------- scratch (device globals: allocation-free, ~260 MB total) ----
__device__ float g_xg0[(size_t)RING_ROWS * GATE_COLS];  // 64 MB ring, layer0 gates
__device__ float g_xg1[(size_t)RING_ROWS * GATE_COLS];  // 64 MB ring, layer1 gates
__device__ float g_y [(size_t)S_TOTAL * 512];           // 128 MB, layer0 output
__device__ float g_z [512 * 512];                       // last-chunk layer1 output
__device__ int   g_prog_xg0[T_DIM];                     // ==64  when xg0 chunk ready
__device__ int   g_prog_y  [T_DIM];                     // ==128 when y chunk ready
__device__ int   g_prog_xg1[T_DIM];                     // ==64  when xg1 chunk ready
__device__ int   g_done0   [T_DIM];                     // ==16  when layer0 read chunk
__device__ int   g_done1   [T_DIM];                     // ==16  when layer1 read chunk

// ---------------- PTX helpers ----------------
static __device__ __forceinline__ uint32_t su32(const void* p) {
    uint32_t a;
    asm("{ .reg .u64 t; cvta.to.shared.u64 t, %1; cvt.u32.u64 %0, t; }" : "=r"(a) : "l"(p));
    return a;
}
static __device__ __forceinline__ uint32_t mapa_rank(uint32_t laddr, uint32_t rank) {
    uint32_t r;
    asm("mapa.shared::cluster.u32 %0, %1, %2;" : "=r"(r) : "r"(laddr), "r"(rank));
    return r;
}
static __device__ __forceinline__ void st_cl(uint32_t addr, float v) {
    asm volatile("st.shared::cluster.f32 [%0], %1;" :: "r"(addr), "f"(v) : "memory");
}
static __device__ __forceinline__ void mbar_init(uint32_t bar, uint32_t cnt) {
    asm volatile("mbarrier.init.shared.b64 [%0], %1;" :: "r"(bar), "r"(cnt) : "memory");
}
static __device__ __forceinline__ void arrive_rel(uint32_t remote_bar) {
    asm volatile("mbarrier.arrive.release.cluster.shared::cluster.b64 _, [%0];"
                 :: "r"(remote_bar) : "memory");
}
static __device__ __forceinline__ void mbar_wait(uint32_t bar, uint32_t parity) {
    asm volatile(
        "{\n\t.reg .pred P;\n\t"
        "WL%=:\n\t"
        "mbarrier.try_wait.parity.acquire.cluster.shared::cta.b64 P, [%0], %1;\n\t"
        "@!P bra WL%=;\n\t}"
        :: "r"(bar), "r"(parity) : "memory");
}
#define CLUSTER_SYNC() do { \
    asm volatile("barrier.cluster.arrive.aligned;" ::: "memory"); \
    asm volatile("barrier.cluster.wait.aligned;"   ::: "memory"); \
} while (0)

static __device__ __forceinline__ int ld_acq(const int* p) {
    int v;
    asm volatile("ld.acquire.gpu.b32 %0, [%1];" : "=r"(v) : "l"(p) : "memory");
    return v;
}
static __device__ __forceinline__ void signal_rel(int* p) {
    __threadfence();
    atomicAdd(p, 1);
}
static __device__ __forceinline__ void wait_ge(const int* p, int target) {
    while (ld_acq(p) < target) __nanosleep(64);
}

static __device__ __forceinline__ unsigned long long pk2(float a, float b) {
    unsigned long long r;
    asm("mov.b64 %0, {%1, %2};" : "=l"(r) : "f"(a), "f"(b));
    return r;
}
static __device__ __forceinline__ void upk2(unsigned long long v, float& a, float& b) {
    asm("mov.b64 {%0, %1}, %2;" : "=f"(a), "=f"(b) : "l"(v));
}
static __device__ __forceinline__ void fma2(unsigned long long& d,
                                            unsigned long long a, unsigned long long b) {
    asm("fma.rn.f32x2 %0, %1, %2, %3;" : "=l"(d) : "l"(a), "l"(b), "l"(d));
}

static __device__ __forceinline__ float sigf(float x) {
    return __fdividef(1.f, 1.f + __expf(-x));
}
static __device__ __forceinline__ float tanhf_fast(float x) {
    return __fdividef(2.f, 1.f + __expf(-2.f * x)) - 1.f;
}

// xg column mapping (per direction block of 1024 cols):
//   cc = R*128 + w*16 + gate*4 + u  <->  whh row = gate*256 + R*32 + w*4 + u
static __device__ __forceinline__ int wrow_of(int cc) {
    return ((cc & 15) >> 2) * 256 + (cc >> 7) * 32 + (((cc >> 4) & 7) << 2) + (cc & 3);
}

// ---------------- init: zero progress counters (deterministic across replays) ----
__global__ void init_prog() {
    int i = threadIdx.x;
    if (i < T_DIM) {
        g_prog_xg0[i] = 0; g_prog_y[i] = 0; g_prog_xg1[i] = 0;
        g_done0[i] = 0;    g_done1[i] = 0;
    }
}

// ---------------- GEMM worker: chunk-ordered 128x128 tiles into a ring --------
static __device__ void gemm_worker(
    const float* __restrict__ Asrc, int xmode,
    const float* __restrict__ wF, const float* __restrict__ wB,
    const float* __restrict__ bF, const float* __restrict__ bB,
    int K, float* __restrict__ dst,
    const int* __restrict__ prog_dep, int dep_target,
    const int* __restrict__ free_dep,
    int* __restrict__ prog_out,
    int wid, int nworkers,
    float (*As)[128], float (*Bs)[128])
{
    const int tid = threadIdx.x;
    const int tx = tid & 15, ty = tid >> 4;
    const int lr = tid >> 1;
    const int lk = (tid & 1) * 4;

    for (int g = wid; g < 8192; g += nworkers) {
        const int tck = g >> 6, e = g & 63;
        const int rowB = ((tck << 2) + (e >> 4)) * 128;
        const int colB = (e & 15) * 128;

        if (tid == 0) {
            if (prog_dep) wait_ge(&prog_dep[tck], dep_target);
            if (tck >= RING_CH) wait_ge(&free_dep[tck - RING_CH], 16);
        }
        __syncthreads();

        const float* arow;
        {
            int r = rowB + lr;
            if (xmode) {  // x is [A, T, I]; step row s = t*512 + a -> x[a, t, :]
                int tt = r >> 9, aa = r & 511;
                arow = Asrc + (size_t)aa * (T_DIM * I_DIM) + (size_t)tt * I_DIM;
            } else {
                arow = Asrc + (size_t)r * 512;
            }
        }
        const float* brow;
        {
            int c = colB + lr;
            int d = c >> 10, cc = c & 1023;
            brow = (d ? wB : wF) + (size_t)wrow_of(cc) * K;
        }

        float acc[8][8];
        #pragma unroll
        for (int i = 0; i < 8; i++)
            #pragma unroll
            for (int j = 0; j < 8; j++) acc[i][j] = 0.f;

        for (int k0 = 0; k0 < K; k0 += 8) {
            __syncthreads();   // guards As/Bs reuse
            float4 av = *(const float4*)(arow + k0 + lk);
            float4 bv = *(const float4*)(brow + k0 + lk);
            As[lk + 0][lr] = av.x; As[lk + 1][lr] = av.y;
            As[lk + 2][lr] = av.z; As[lk + 3][lr] = av.w;
            Bs[lk + 0][lr] = bv.x; Bs[lk + 1][lr] = bv.y;
            Bs[lk + 2][lr] = bv.z; Bs[lk + 3][lr] = bv.w;
            __syncthreads();
            #pragma unroll
            for (int kk = 0; kk < 8; kk++) {
                float ar[8], br[8];
                #pragma unroll
                for (int i = 0; i < 8; i++) ar[i] = As[kk][ty * 8 + i];
                #pragma unroll
                for (int j = 0; j < 8; j++) br[j] = Bs[kk][tx * 8 + j];
                #pragma unroll
                for (int i = 0; i < 8; i++)
                    #pragma unroll
                    for (int j = 0; j < 8; j++) acc[i][j] = fmaf(ar[i], br[j], acc[i][j]);
            }
        }

        #pragma unroll
        for (int j = 0; j < 8; j++) {
            int c = colB + tx * 8 + j;
            int d = c >> 10, cc = c & 1023;
            float bb = __ldg((d ? bB : bF) + wrow_of(cc));
            #pragma unroll
            for (int i = 0; i < 8; i++) {
                int r = rowB + ty * 8 + i;
                dst[(size_t)(r & RING_MASK) * GATE_COLS + c] = acc[i][j] + bb;
            }
        }
        __syncthreads();   // all threads' global stores precede the release signal
        if (tid == 0) signal_rel(&prog_out[tck]);
    }
}

// ---------------- Recurrent runner (one CTA of an 8-CTA cluster) ----------------
// R8 protocol + widened lanes: all 32 lanes redundantly compute activations and
// carry c_reg for unit l&3, so the 4-unit x 8-peer broadcast is ONE predicated
// DSMEM store warp-instruction (lane l -> unit l&3 at peer l>>2).
static __device__ void lstm_run(
    const float* __restrict__ whh, const float* __restrict__ xg,
    const int* __restrict__ prog_in, int* __restrict__ done_in,
    int* __restrict__ prog_out,
    int dir, int R, int lastOnly,
    float (*h_buf)[256], unsigned long long* mbarp)
{
    const int t     = threadIdx.x;
    const int w     = t >> 5;
    const int l     = t & 31;
    const int r     = l & 15;              // gate*4 + uidx
    const int khalf = l >> 4;
    const int gate  = r >> 2, uidx = r & 3;
    const int grow  = gate * 256 + R * 32 + w * 4 + uidx;   // row in whh [1024][256]
    const int dirMask = dir ? 511 : 0;                      // data row = s ^ dirMask

    // Whh slice -> registers, packed f32x2 (128 floats = 64 u64 per thread)
    unsigned long long wr_[64];
    {
        const float4* wp = (const float4*)(whh + (size_t)grow * 256 + khalf * 128);
        #pragma unroll
        for (int i = 0; i < 32; i++) {
            float4 v = wp[i];
            wr_[2 * i]     = pk2(v.x, v.y);
            wr_[2 * i + 1] = pk2(v.z, v.w);
        }
    }

    h_buf[0][t] = 0.f;                          // h0 = 0
    if (t == 0) mbar_init(su32(mbarp), 8);      // ONE arrive per producer CTA per step
    __syncthreads();
    CLUSTER_SYNC();                             // barriers visible cluster-wide

    const uint32_t hb  = su32(&h_buf[0][0]);
    const uint32_t bar = su32(mbarp);
    uint32_t ph[8], pb[8];
    #pragma unroll
    for (int j = 0; j < 8; j++) { ph[j] = mapa_rank(hb, j); pb[j] = mapa_rank(bar, j); }

    // this lane's xg element: col = R*128 + w*16 + r (per direction block)
    const float* xgp = xg + (size_t)dir * 1024 + R * 128 + w * 16 + r;

    const int u     = l & 3;                    // this lane's owned unit index
    const int peer  = l >> 2;                   // this lane's broadcast target CTA
    const int unit  = R * 32 + w * 4 + u;       // global unit id (valid on ALL lanes)
    // lane l stores unit u into peer's h slot; slot parity term added per step
    const uint32_t bcast_base = (uint32_t)(unit * 4);

    float c_reg = 0.f;                          // redundant per-unit cell state
    float xc = 0.f, xn = 0.f;

    for (int s = 0; s < S_TOTAL; s++) {
        if ((s & 511) == 0) {                   // chunk boundary
            int tck = s >> 9;
            if (t == 0) wait_ge(&prog_in[tck], 64);
            __syncthreads();                    // all warps past all chunk tck-1 reads
            if (t == 0 && tck > 0) signal_rel(&done_in[tck - 1]);
            xc = __ldg(xgp + (size_t)((s ^ dirMask) & RING_MASK) * GATE_COLS);
            xn = __ldg(xgp + (size_t)(((s + 1) ^ dirMask) & RING_MASK) * GATE_COLS);
        }
        float xf = 0.f;                         // speculative (discarded at boundary)
        if (s + 2 < S_TOTAL)
            xf = __ldg(xgp + (size_t)(((s + 2) ^ dirMask) & RING_MASK) * GATE_COLS);

        if (s > 0) mbar_wait(bar, (uint32_t)((s - 1) & 1));

        // 128-MAC dot over this lane's k-half, dual accumulator chains
        const ulonglong2* hp = (const ulonglong2*)&h_buf[s & 1][khalf * 128];
        unsigned long long acc0 = 0ull, acc1 = 0ull;
        #pragma unroll
        for (int i = 0; i < 32; i++) {
            ulonglong2 hv = hp[i];
            fma2(acc0, wr_[2 * i],     hv.x);
            fma2(acc1, wr_[2 * i + 1], hv.y);
        }
        float a0, a1, a2, a3;
        upk2(acc0, a0, a1); upk2(acc1, a2, a3);
        float v = (a0 + a1) + (a2 + a3);
        v += __shfl_xor_sync(0xffffffffu, v, 16);       // combine k-halves
        float g = v + xc;
        xc = xn; xn = xf;

        // transpose gates: every lane gathers all 4 gate rows of unit u
        float gi = __shfl_sync(0xffffffffu, g, u);
        float gf = __shfl_sync(0xffffffffu, g, 4 + u);
        float gg = __shfl_sync(0xffffffffu, g, 8 + u);
        float go = __shfl_sync(0xffffffffu, g, 12 + u);

        // ALL lanes compute activations + cell state for unit u (redundant,
        // deterministic) so hn is available warp-wide for the 1-instr broadcast
        float fi = sigf(gi), ff = sigf(gf), fo = sigf(go), tg = tanhf_fast(gg);
        c_reg = ff * c_reg + fi * tg;
        float hn = fo * tanhf_fast(c_reg);

        // one-instruction broadcast: lane l -> unit u at peer l>>2, slot (s+1)&1
        st_cl(ph[peer] + (uint32_t)(((s + 1) & 1) * 1024) + bcast_base, hn);

        // g_y / g_z store off the critical path (ordered before signal by syncthreads)
        if (l < 4) {
            int orow = s ^ dirMask;
            if (!lastOnly)
                g_y[(size_t)orow * 512 + dir * 256 + unit] = hn;
            else if (orow >= S_TOTAL - 512)
                g_z[(orow - (S_TOTAL - 512)) * 512 + dir * 256 + unit] = hn;
        }
        __syncthreads();                        // ALL warps' stores precede the arrives
        if (prog_out && (s & 511) == 511 && l == 0)
            signal_rel(&prog_out[s >> 9]);      // this warp's y-chunk writes done
        if (w == 0 && l < 8) arrive_rel(pb[l]); // warp 0: one arrive per peer CTA
    }
    CLUSTER_SYNC();  // no CTA exits while peers may still write its SMEM
}

// ---------------- Persistent mega-kernel: layer0 || gemm0 || gemm1 || layer1 ----
__global__ void __launch_bounds__(256, 1) __cluster_dims__(8, 1, 1)
mega(const float* __restrict__ x,
     const float* __restrict__ wih0f, const float* __restrict__ wih0b,
     const float* __restrict__ b0f,   const float* __restrict__ b0b,
     const float* __restrict__ whh0f, const float* __restrict__ whh0b,
     const float* __restrict__ wih1f, const float* __restrict__ wih1b,
     const float* __restrict__ b1f,   const float* __restrict__ b1b,
     const float* __restrict__ whh1f, const float* __restrict__ whh1b)
{
    __shared__ float As[8][128];
    __shared__ float Bs[8][128];
    __shared__ __align__(16) float h_buf[2][256];
    __shared__ __align__(8) unsigned long long mbar;

    const int cta = blockIdx.x;
    if (cta < 16) {                       // layer0 recurrence (clusters 0,1)
        int dir = cta >> 3, R = cta & 7;
        lstm_run(dir ? whh0b : whh0f, g_xg0, g_prog_xg0, g_done0, g_prog_y,
                 dir, R, 0, h_buf, &mbar);
    } else if (cta < 32) {                // layer1 recurrence (clusters 2,3)
        int c = cta - 16;
        int dir = c >> 3, R = c & 7;
        lstm_run(dir ? whh1b : whh1f, g_xg1, g_prog_xg1, g_done1, nullptr,
                 dir, R, 1, h_buf, &mbar);
    } else if (cta < 64) {                // 32 workers: xg0 = x @ Wih0^T + b0
        gemm_worker(x, 1, wih0f, wih0b, b0f, b0b, I_DIM, g_xg0,
                    nullptr, 0, g_done0, g_prog_xg0, cta - 32, 32, As, Bs);
    } else {                              // 32 workers: xg1 = y @ Wih1^T + b1
        gemm_worker(g_y, 0, wih1f, wih1b, b1f, b1b, 512, g_xg1,
                    g_prog_y, 128, g_done1, g_prog_xg1, cta - 64, 32, As, Bs);
    }
}

// ---------------- Head: z[512,512] @ w1.T + b1 -> @ w2.T + b2 -> softmax(13) ----
__global__ void __launch_bounds__(128)
head_kernel(const float* __restrict__ w1, const float* __restrict__ b1,
            const float* __restrict__ w2, const float* __restrict__ b2,
            float* __restrict__ out)
{
    __shared__ float zr[512];
    __shared__ float hd[128];
    __shared__ float lg[16];
    const int a = blockIdx.x, t = threadIdx.x;

    for (int i = t; i < 512; i += 128) zr[i] = g_z[a * 512 + i];
    __syncthreads();

    float acc = __ldg(b1 + t);
    const float* wr = w1 + (size_t)t * 512;
    #pragma unroll 8
    for (int k = 0; k < 512; k++) acc = fmaf(__ldg(wr + k), zr[k], acc);
    hd[t] = acc;
    __syncthreads();

    if (t < 13) {
        float lgt = __ldg(b2 + t);
        const float* w2r = w2 + t * 128;
        #pragma unroll 8
        for (int k = 0; k < 128; k++) lgt = fmaf(__ldg(w2r + k), hd[k], lgt);
        lg[t] = lgt;
    }
    __syncthreads();
    if (t < 13) {
        float m = -1e30f;
        for (int j = 0; j < 13; j++) m = fmaxf(m, lg[j]);
        float ssum = 0.f;
        for (int j = 0; j < 13; j++) ssum += expf(lg[j] - m);
        out[a * 13 + t] = expf(lg[t] - m) / ssum;
    }
}

// ---------------- launch ----------------
extern "C" void kernel_launch(void* const* d_in, const int* in_sizes, int n_in,
                              void* d_out, int out_size)
{
    const float* x     = (const float*)d_in[0];
    const float* wih0f = (const float*)d_in[1];
    const float* whh0f = (const float*)d_in[2];
    const float* b0f   = (const float*)d_in[3];
    const float* wih0b = (const float*)d_in[4];
    const float* whh0b = (const float*)d_in[5];
    const float* b0b   = (const float*)d_in[6];
    const float* wih1f = (const float*)d_in[7];
    const float* whh1f = (const float*)d_in[8];
    const float* b1f   = (const float*)d_in[9];
    const float* wih1b = (const float*)d_in[10];
    const float* whh1b = (const float*)d_in[11];
    const float* b1b   = (const float*)d_in[12];
    const float* w1    = (const float*)d_in[13];
    const float* bias1 = (const float*)d_in[14];
    const float* w2    = (const float*)d_in[15];
    const float* bias2 = (const float*)d_in[16];
    float* out = (float*)d_out;

    init_prog<<<1, 128>>>();
    mega<<<96, 256>>>(x, wih0f, wih0b, b0f, b0b, whh0f, whh0b,
                      wih1f, wih1b, b1f, b1b, whh1f, whh1b);
    head_kernel<<<512, 128>>>(w1, bias1, w2, bias2, out);
}